// round 1
// baseline (speedup 1.0000x reference)
#include <cuda_runtime.h>
#include <math.h>

// ---------------------------------------------------------------------------
// SanaBlock: LN+adaLN -> LiteLA -> cross-attn -> GLUMBConv, B=2,N=4096,C=1152
// ---------------------------------------------------------------------------
constexpr int Bb   = 2;
constexpr int Nn   = 4096;
constexpr int Cc   = 1152;
constexpr int Mkv  = 300;
constexpr int HIDd = 2880;
constexpr int HLA  = 36;   // LiteLA heads, d=32
constexpr int HX   = 16;   // cross heads, d=72

// Scratch: lifetime-aliased static device buffers.
// g_big: qkv (28.3M f) -> scores (39.3M f) -> h (47.2M f)
__device__ float g_big[47185920];
// g_sh: xmod1 -> la_out -> q -> cross_o -> xmod2
__device__ float g_sh [(size_t)Bb * Nn * Cc];
__device__ float g_x1 [(size_t)Bb * Nn * Cc];
__device__ float g_x2 [(size_t)Bb * Nn * Cc];
__device__ float g_glu[(size_t)Bb * Nn * HIDd];
__device__ float g_kvb[(size_t)Bb * Mkv * 2 * Cc];
__device__ float g_vk [Bb * HLA * 33 * 32];
__device__ float g_mb [Bb * 6 * Cc];

// ---------------------------------------------------------------------------
// m = sst + t  (B,6,C)
// ---------------------------------------------------------------------------
__global__ void mod_kernel(const float* __restrict__ t, const float* __restrict__ sst)
{
    int i = blockIdx.x * 256 + threadIdx.x;
    if (i < Bb * 6 * Cc) g_mb[i] = sst[i % (6 * Cc)] + t[i];
}

// ---------------------------------------------------------------------------
// LayerNorm (no affine) + adaLN modulate: out = ln(x)*(1+sc)+sh
// ---------------------------------------------------------------------------
__global__ __launch_bounds__(256)
void ln_mod_kernel(const float* __restrict__ in, float* __restrict__ out,
                   int scRow, int shRow)
{
    int row = blockIdx.x;
    int b   = row / Nn;
    const float* xr = in + (size_t)row * Cc;

    float s = 0.f, s2 = 0.f;
    for (int c = threadIdx.x; c < Cc; c += blockDim.x) {
        float v = xr[c]; s += v; s2 += v * v;
    }
    __shared__ float sh1[8], sh2[8];
    int lane = threadIdx.x & 31, wid = threadIdx.x >> 5;
    #pragma unroll
    for (int o = 16; o > 0; o >>= 1) {
        s  += __shfl_down_sync(0xffffffffu, s,  o);
        s2 += __shfl_down_sync(0xffffffffu, s2, o);
    }
    if (lane == 0) { sh1[wid] = s; sh2[wid] = s2; }
    __syncthreads();
    if (wid == 0) {
        s  = (lane < 8) ? sh1[lane] : 0.f;
        s2 = (lane < 8) ? sh2[lane] : 0.f;
        #pragma unroll
        for (int o = 4; o > 0; o >>= 1) {
            s  += __shfl_down_sync(0xffffffffu, s,  o);
            s2 += __shfl_down_sync(0xffffffffu, s2, o);
        }
        if (lane == 0) { sh1[0] = s; sh2[0] = s2; }
    }
    __syncthreads();
    float mu   = sh1[0] * (1.f / Cc);
    float var  = sh2[0] * (1.f / Cc) - mu * mu;
    float rstd = rsqrtf(var + 1e-6f);
    const float* mb = g_mb + (size_t)b * 6 * Cc;
    for (int c = threadIdx.x; c < Cc; c += blockDim.x) {
        float sc = mb[scRow * Cc + c];
        float sv = mb[shRow * Cc + c];
        out[(size_t)row * Cc + c] = (xr[c] - mu) * rstd * (1.f + sc) + sv;
    }
}

// ---------------------------------------------------------------------------
// Generic tiled GEMM: O = epi(A * op(B) + bias)
//   TRANSB=1: O[i,j] = sum_k A[i,k]*Bm[j,k]
//   TRANSB=0: O[i,j] = sum_k A[i,k]*Bm[k,j]
// EPI: 0 none, 1 silu, 2 res+v, 3 res+gate*v
// BM=BN=128, BK=8, 8x8 per thread, 256 threads.
// ---------------------------------------------------------------------------
template<bool TRANSB, bool BIAS, int EPI>
__global__ __launch_bounds__(256)
void gemm_k(const float* __restrict__ A, const float* __restrict__ Bm,
            const float* __restrict__ bias, const float* __restrict__ res,
            const float* __restrict__ gate, float* __restrict__ O,
            int Mrows, int Nout, int K, int lda, int ldb, int ldo,
            int HB, long aBs, long aHs, long bBs, long bHs, long oBs, long oHs,
            int gateStride)
{
    __shared__ float As[8][128];
    __shared__ float Bs[8][128];
    if (gridDim.z > 1) {
        int z = blockIdx.z;
        int bI = z / HB, hI = z % HB;
        A  += bI * aBs + hI * aHs;
        Bm += bI * bBs + hI * bHs;
        O  += bI * oBs + hI * oHs;
    }
    int m0  = blockIdx.y * 128;
    int n0  = blockIdx.x * 128;
    int tid = threadIdx.x;
    int tx  = tid & 15, ty = tid >> 4;
    int lr  = tid >> 1;
    int lk  = (tid & 1) * 4;
    int nk  = tid >> 5;
    int nj  = (tid & 31) * 4;

    float acc[8][8];
    #pragma unroll
    for (int i = 0; i < 8; i++)
        #pragma unroll
        for (int j = 0; j < 8; j++) acc[i][j] = 0.f;

    for (int k0 = 0; k0 < K; k0 += 8) {
        {
            int gr = m0 + lr;
            #pragma unroll
            for (int i = 0; i < 4; i++) {
                int gk = k0 + lk + i;
                As[lk + i][lr] = (gr < Mrows && gk < K) ? A[(long)gr * lda + gk] : 0.f;
            }
        }
        if (TRANSB) {
            int gj = n0 + lr;
            #pragma unroll
            for (int i = 0; i < 4; i++) {
                int gk = k0 + lk + i;
                Bs[lk + i][lr] = (gj < Nout && gk < K) ? Bm[(long)gj * ldb + gk] : 0.f;
            }
        } else {
            int gk = k0 + nk;
            #pragma unroll
            for (int i = 0; i < 4; i++) {
                int gj = n0 + nj + i;
                Bs[nk][nj + i] = (gk < K && gj < Nout) ? Bm[(long)gk * ldb + gj] : 0.f;
            }
        }
        __syncthreads();
        #pragma unroll
        for (int kk = 0; kk < 8; kk++) {
            float af[8], bf[8];
            *(float4*)&af[0] = *(const float4*)&As[kk][ty * 8];
            *(float4*)&af[4] = *(const float4*)&As[kk][ty * 8 + 4];
            *(float4*)&bf[0] = *(const float4*)&Bs[kk][tx * 8];
            *(float4*)&bf[4] = *(const float4*)&Bs[kk][tx * 8 + 4];
            #pragma unroll
            for (int i = 0; i < 8; i++)
                #pragma unroll
                for (int j = 0; j < 8; j++)
                    acc[i][j] = fmaf(af[i], bf[j], acc[i][j]);
        }
        __syncthreads();
    }

    #pragma unroll
    for (int i = 0; i < 8; i++) {
        int row = m0 + ty * 8 + i;
        if (row >= Mrows) continue;
        #pragma unroll
        for (int j = 0; j < 8; j++) {
            int col = n0 + tx * 8 + j;
            if (col >= Nout) continue;
            float v = acc[i][j];
            if (BIAS) v += bias[col];
            if (EPI == 1) v = v / (1.f + __expf(-v));
            if (EPI == 2) v = res[(long)row * ldo + col] + v;
            if (EPI == 3) {
                int bI = row / Nn;
                v = res[(long)row * ldo + col] + gate[bI * gateStride + col] * v;
            }
            O[(long)row * ldo + col] = v;
        }
    }
}

// ---------------------------------------------------------------------------
// LiteLA vk accumulation (split-K over N with atomics)
// ---------------------------------------------------------------------------
__global__ void zero_vk_kernel()
{
    int i = blockIdx.x * 256 + threadIdx.x;
    if (i < Bb * HLA * 33 * 32) g_vk[i] = 0.f;
}

__global__ __launch_bounds__(256)
void vk_kernel(const float* __restrict__ qkv, float* __restrict__ vkout)
{
    int bh = blockIdx.x;
    int b  = bh / HLA, h = bh % HLA;
    int split = blockIdx.y;
    __shared__ float ks[32][33];
    __shared__ float vs[32][33];
    float acc[5] = {0.f, 0.f, 0.f, 0.f, 0.f};
    int tid = threadIdx.x;
    const size_t base = (size_t)b * Nn * 3 * Cc;
    int nStart = split * (Nn / 16);
    for (int n0 = nStart; n0 < nStart + Nn / 16; n0 += 32) {
        for (int li = tid; li < 1024; li += 256) {
            int nn = li >> 5, dc = li & 31;
            size_t off = base + (size_t)(n0 + nn) * 3 * Cc + h * 32 + dc;
            ks[nn][dc] = fmaxf(qkv[off + Cc], 0.f);
            vs[nn][dc] = qkv[off + 2 * Cc];
        }
        __syncthreads();
        #pragma unroll
        for (int u = 0; u < 5; u++) {
            int idx = tid + 256 * u;
            if (idx < 1056) {
                int e = idx >> 5, dc = idx & 31;
                float a = acc[u];
                if (e == 32) {
                    #pragma unroll
                    for (int nn = 0; nn < 32; nn++) a += ks[nn][dc];
                } else {
                    #pragma unroll
                    for (int nn = 0; nn < 32; nn++) a += vs[nn][e] * ks[nn][dc];
                }
                acc[u] = a;
            }
        }
        __syncthreads();
    }
    #pragma unroll
    for (int u = 0; u < 5; u++) {
        int idx = tid + 256 * u;
        if (idx < 1056) {
            int e = idx >> 5, dc = idx & 31;
            atomicAdd(&vkout[((size_t)bh * 33 + e) * 32 + dc], acc[u]);
        }
    }
}

__global__ __launch_bounds__(256)
void la_out_kernel(const float* __restrict__ qkv, const float* __restrict__ vk,
                   float* __restrict__ out)
{
    int row = blockIdx.x;
    int b   = row / Nn;
    __shared__ float q[Cc];
    __shared__ float den[HLA];
    const float* qr = qkv + (size_t)row * 3 * Cc;
    for (int c = threadIdx.x; c < Cc; c += blockDim.x) q[c] = fmaxf(qr[c], 0.f);
    __syncthreads();
    if (threadIdx.x < HLA) {
        int h = threadIdx.x;
        const float* vkh = vk + ((size_t)(b * HLA + h) * 33 + 32) * 32;
        float s = 0.f;
        #pragma unroll
        for (int d = 0; d < 32; d++) s += vkh[d] * q[h * 32 + d];
        den[h] = s + 1e-8f;
    }
    __syncthreads();
    for (int c = threadIdx.x; c < Cc; c += blockDim.x) {
        int h = c >> 5, dd = c & 31;
        const float* vkr = vk + ((size_t)(b * HLA + h) * 33 + dd) * 32;
        const float* qh  = q + h * 32;
        float s = 0.f;
        #pragma unroll
        for (int d = 0; d < 32; d++) s += vkr[d] * qh[d];
        out[(size_t)row * Cc + c] = s / den[h];
    }
}

// ---------------------------------------------------------------------------
// Cross-attn softmax over M=300 (one warp per row), scale=1/sqrt(72)
// ---------------------------------------------------------------------------
__global__ __launch_bounds__(256)
void softmax_kernel(float* __restrict__ s, long rows)
{
    long gw  = ((long)blockIdx.x * blockDim.x + threadIdx.x) >> 5;
    int lane = threadIdx.x & 31;
    if (gw >= rows) return;
    float* r = s + gw * Mkv;
    const float scale = 0.11785113019775793f;
    float v[10];
    float mx = -1e30f;
    #pragma unroll
    for (int i = 0; i < 10; i++) {
        int m = lane + 32 * i;
        v[i] = (m < Mkv) ? r[m] * scale : -1e30f;
        mx = fmaxf(mx, v[i]);
    }
    #pragma unroll
    for (int o = 16; o > 0; o >>= 1) mx = fmaxf(mx, __shfl_xor_sync(0xffffffffu, mx, o));
    float sum = 0.f;
    #pragma unroll
    for (int i = 0; i < 10; i++) { v[i] = __expf(v[i] - mx); sum += v[i]; }
    #pragma unroll
    for (int o = 16; o > 0; o >>= 1) sum += __shfl_xor_sync(0xffffffffu, sum, o);
    float inv = 1.f / sum;
    #pragma unroll
    for (int i = 0; i < 10; i++) {
        int m = lane + 32 * i;
        if (m < Mkv) r[m] = v[i] * inv;
    }
}

// ---------------------------------------------------------------------------
// depthwise 3x3 (SAME, 64x64) + bias + GLU
// ---------------------------------------------------------------------------
__global__ __launch_bounds__(256)
void dwglu_kernel(const float* __restrict__ h, const float* __restrict__ dww,
                  const float* __restrict__ dwb, float* __restrict__ out)
{
    long idx = (long)blockIdx.x * 256 + threadIdx.x;
    if (idx >= (long)Bb * Nn * HIDd) return;
    int  ch = (int)(idx % HIDd);
    long bn = idx / HIDd;
    int  n  = (int)(bn % Nn);
    int  b  = (int)(bn / Nn);
    int  y  = n >> 6, x = n & 63;
    float accA = dwb[ch];
    float accG = dwb[ch + HIDd];
    const float* wA = dww + (size_t)ch * 9;
    const float* wG = dww + (size_t)(ch + HIDd) * 9;
    #pragma unroll
    for (int dy = -1; dy <= 1; dy++) {
        int yy = y + dy;
        if (yy < 0 || yy > 63) continue;
        #pragma unroll
        for (int dx = -1; dx <= 1; dx++) {
            int xx = x + dx;
            if (xx < 0 || xx > 63) continue;
            size_t off = ((size_t)b * Nn + yy * 64 + xx) * (2 * HIDd);
            int w = (dy + 1) * 3 + (dx + 1);
            accA += h[off + ch]        * wA[w];
            accG += h[off + ch + HIDd] * wG[w];
        }
    }
    out[idx] = accA * (accG / (1.f + __expf(-accG)));
}

// ---------------------------------------------------------------------------
extern "C" void kernel_launch(void* const* d_in, const int* /*in_sizes*/, int /*n_in*/,
                              void* d_out, int /*out_size*/)
{
    const float* x       = (const float*)d_in[0];
    const float* y       = (const float*)d_in[1];
    const float* t       = (const float*)d_in[2];
    const float* sst     = (const float*)d_in[3];
    const float* qkv_w   = (const float*)d_in[4];
    const float* aproj_w = (const float*)d_in[5];
    const float* aproj_b = (const float*)d_in[6];
    const float* q_w     = (const float*)d_in[7];
    const float* q_b     = (const float*)d_in[8];
    const float* kv_w    = (const float*)d_in[9];
    const float* kv_b    = (const float*)d_in[10];
    const float* cproj_w = (const float*)d_in[11];
    const float* cproj_b = (const float*)d_in[12];
    const float* inv_w   = (const float*)d_in[13];
    const float* inv_b   = (const float*)d_in[14];
    const float* dw_w    = (const float*)d_in[15];
    const float* dw_b    = (const float*)d_in[16];
    const float* pw_w    = (const float*)d_in[17];
    float* out = (float*)d_out;

    float *p_big, *p_sh, *p_x1, *p_x2, *p_glu, *p_kv, *p_vk, *p_m;
    cudaGetSymbolAddress((void**)&p_big, g_big);
    cudaGetSymbolAddress((void**)&p_sh,  g_sh);
    cudaGetSymbolAddress((void**)&p_x1,  g_x1);
    cudaGetSymbolAddress((void**)&p_x2,  g_x2);
    cudaGetSymbolAddress((void**)&p_glu, g_glu);
    cudaGetSymbolAddress((void**)&p_kv,  g_kvb);
    cudaGetSymbolAddress((void**)&p_vk,  g_vk);
    cudaGetSymbolAddress((void**)&p_m,   g_mb);

    const int ROWS = Bb * Nn;  // 8192

    mod_kernel<<<(Bb * 6 * Cc + 255) / 256, 256>>>(t, sst);
    ln_mod_kernel<<<ROWS, 256>>>(x, p_sh, 1, 0);

    // qkv = xmod1 @ qkv_w.T
    gemm_k<true, false, 0><<<dim3(27, 64, 1), 256>>>(
        p_sh, qkv_w, nullptr, nullptr, nullptr, p_big,
        ROWS, 3 * Cc, Cc, Cc, Cc, 3 * Cc, 1, 0, 0, 0, 0, 0, 0, 0);

    zero_vk_kernel<<<(Bb * HLA * 33 * 32 + 255) / 256, 256>>>();
    vk_kernel<<<dim3(Bb * HLA, 16), 256>>>(p_big, p_vk);
    la_out_kernel<<<ROWS, 256>>>(p_big, p_vk, p_sh);

    // x1 = x + g_a * (la @ aproj_w.T + b)
    gemm_k<true, true, 3><<<dim3(9, 64, 1), 256>>>(
        p_sh, aproj_w, aproj_b, x, p_m + 2 * Cc, p_x1,
        ROWS, Cc, Cc, Cc, Cc, Cc, 1, 0, 0, 0, 0, 0, 0, 6 * Cc);

    // q = x1 @ q_w.T + q_b
    gemm_k<true, true, 0><<<dim3(9, 64, 1), 256>>>(
        p_x1, q_w, q_b, nullptr, nullptr, p_sh,
        ROWS, Cc, Cc, Cc, Cc, Cc, 1, 0, 0, 0, 0, 0, 0, 0);

    // kv = y @ kv_w.T + kv_b
    gemm_k<true, true, 0><<<dim3(18, 5, 1), 256>>>(
        y, kv_w, kv_b, nullptr, nullptr, p_kv,
        Bb * Mkv, 2 * Cc, Cc, Cc, Cc, 2 * Cc, 1, 0, 0, 0, 0, 0, 0, 0);

    // scores[b,h] = q @ k.T (batched)
    gemm_k<true, false, 0><<<dim3(3, 32, Bb * HX), 256>>>(
        p_sh, p_kv, nullptr, nullptr, nullptr, p_big,
        Nn, Mkv, 72, Cc, 2 * Cc, Mkv,
        HX, (long)Nn * Cc, 72, (long)Mkv * 2 * Cc, 72,
        (long)HX * Nn * Mkv, (long)Nn * Mkv, 0);

    softmax_kernel<<<(Bb * HX * Nn) / 8, 256>>>(p_big, (long)Bb * HX * Nn);

    // o[b,h] = a @ v (batched NN)
    gemm_k<false, false, 0><<<dim3(1, 32, Bb * HX), 256>>>(
        p_big, p_kv + Cc, nullptr, nullptr, nullptr, p_sh,
        Nn, 72, Mkv, Mkv, 2 * Cc, Cc,
        HX, (long)HX * Nn * Mkv, (long)Nn * Mkv, (long)Mkv * 2 * Cc, 72,
        (long)Nn * Cc, 72, 0);

    // x2 = x1 + o @ cproj_w.T + b
    gemm_k<true, true, 2><<<dim3(9, 64, 1), 256>>>(
        p_sh, cproj_w, cproj_b, p_x1, nullptr, p_x2,
        ROWS, Cc, Cc, Cc, Cc, Cc, 1, 0, 0, 0, 0, 0, 0, 0);

    ln_mod_kernel<<<ROWS, 256>>>(p_x2, p_sh, 4, 3);

    // h = silu(xmod2 @ inv_w.T + b)
    gemm_k<true, true, 1><<<dim3(45, 64, 1), 256>>>(
        p_sh, inv_w, inv_b, nullptr, nullptr, p_big,
        ROWS, 2 * HIDd, Cc, Cc, Cc, 2 * HIDd, 1, 0, 0, 0, 0, 0, 0, 0);

    dwglu_kernel<<<(int)(((long)Bb * Nn * HIDd + 255) / 256), 256>>>(
        p_big, dw_w, dw_b, p_glu);

    // out = x2 + g_m * (glu @ pw_w.T)
    gemm_k<true, false, 3><<<dim3(9, 64, 1), 256>>>(
        p_glu, pw_w, nullptr, p_x2, p_m + 5 * Cc, out,
        ROWS, Cc, HIDd, HIDd, HIDd, Cc, 1, 0, 0, 0, 0, 0, 0, 6 * Cc);
}

// round 3
// speedup vs baseline: 2.4171x; 2.4171x over previous
#include <cuda_runtime.h>
#include <cstdint>
#include <math.h>

// ---------------------------------------------------------------------------
// SanaBlock: LN+adaLN -> LiteLA -> cross-attn -> GLUMBConv, B=2,N=4096,C=1152
// R3: dense NT GEMMs on mma.sync tf32 (compute_103-portable tensor path)
// ---------------------------------------------------------------------------
constexpr int Bb   = 2;
constexpr int Nn   = 4096;
constexpr int Cc   = 1152;
constexpr int Mkv  = 300;
constexpr int HIDd = 2880;
constexpr int HLA  = 36;
constexpr int HX   = 16;

__device__ float g_big[47185920];
__device__ float g_sh [(size_t)Bb * Nn * Cc];
__device__ float g_x1 [(size_t)Bb * Nn * Cc];
__device__ float g_x2 [(size_t)Bb * Nn * Cc];
__device__ float g_glu[(size_t)Bb * Nn * HIDd];
__device__ float g_kvb[(size_t)Bb * Mkv * 2 * Cc];
__device__ float g_vk [Bb * HLA * 33 * 32];
__device__ float g_mb [Bb * 6 * Cc];

// ---------------------------------------------------------------------------
// helpers
// ---------------------------------------------------------------------------
__device__ __forceinline__ uint32_t smem_u32(const void* p){
    uint32_t a;
    asm("{ .reg .u64 t; cvta.to.shared.u64 t, %1; cvt.u32.u64 %0, t; }"
        : "=r"(a) : "l"(p));
    return a;
}
__device__ __forceinline__ void cp16(uint32_t dst, const void* src, int srcsz){
    asm volatile("cp.async.cg.shared.global [%0], [%1], 16, %2;"
        ::"r"(dst),"l"(src),"r"(srcsz):"memory");
}
#define CP_COMMIT() asm volatile("cp.async.commit_group;":::"memory")
#define CP_WAIT1()  asm volatile("cp.async.wait_group 1;":::"memory")

__device__ __forceinline__ uint32_t f2tf(float f){
    uint32_t u; asm("cvt.rna.tf32.f32 %0, %1;" : "=r"(u) : "f"(f)); return u;
}
__device__ __forceinline__ void mma8(float* d, const uint32_t* a, const uint32_t* b){
    asm volatile("mma.sync.aligned.m16n8k8.row.col.f32.tf32.tf32.f32 "
        "{%0,%1,%2,%3},{%4,%5,%6,%7},{%8,%9},{%0,%1,%2,%3};"
        : "+f"(d[0]),"+f"(d[1]),"+f"(d[2]),"+f"(d[3])
        : "r"(a[0]),"r"(a[1]),"r"(a[2]),"r"(a[3]),"r"(b[0]),"r"(b[1]));
}

// ---------------------------------------------------------------------------
// tf32 mma NT GEMM: O[M,N] = epi(A[M,K]*B[N,K]^T + bias)
// CTA 128x128x32, 8 warps (4M x 2N), warp tile 32x64, 2-stage cp.async.
// smem rows padded to 36 floats (144B) for conflict-free fragment loads.
// EPI: 0 none, 1 silu, 2 +res, 3 +res+gate*v
// ---------------------------------------------------------------------------
constexpr int LDP     = 36;                    // padded row, floats
constexpr int TILE_F  = 128 * LDP;             // floats per (A or B) tile
constexpr int STAGE_F = 2 * TILE_F;            // A+B per stage
constexpr int MM_SMEM = 2 * STAGE_F * 4;       // bytes (73728)

template<bool BIAS, int EPI>
__global__ __launch_bounds__(256)
void mma_gemm(const float* __restrict__ A, const float* __restrict__ Bw,
              const float* __restrict__ bias, const float* __restrict__ res,
              const float* __restrict__ gate, float* __restrict__ O,
              int Mrows, int Nout, int K, int gateStride)
{
    extern __shared__ float smf[];
    uint32_t sbase = smem_u32(smf);
    int tid = threadIdx.x, wid = tid >> 5, lane = tid & 31;
    int warpM = wid >> 1, warpN = wid & 1;
    int m0 = blockIdx.y * 128, n0 = blockIdx.x * 128;

    const int T = K >> 5;       // K % 32 == 0 for all call sites

    auto load_tile = [&](int t, int buf) {
        uint32_t base = sbase + (uint32_t)buf * STAGE_F * 4;
        int k0 = t << 5;
        #pragma unroll
        for (int i = 0; i < 4; i++) {
            int c = tid + (i << 8);         // 0..1023
            int row = c >> 3, kc = c & 7;
            uint32_t dst = base + (uint32_t)(row * LDP + kc * 4) * 4;
            const float* ga = A + (size_t)(m0 + row) * K + k0 + kc * 4;
            cp16(dst, ga, (m0 + row) < Mrows ? 16 : 0);
            uint32_t dstB = dst + TILE_F * 4;
            const float* gb = Bw + (size_t)(n0 + row) * K + k0 + kc * 4;
            cp16(dstB, gb, (n0 + row) < Nout ? 16 : 0);
        }
    };

    float acc[2][8][4];
    #pragma unroll
    for (int mt = 0; mt < 2; mt++)
        #pragma unroll
        for (int nt = 0; nt < 8; nt++)
            #pragma unroll
            for (int q = 0; q < 4; q++) acc[mt][nt][q] = 0.f;

    load_tile(0, 0); CP_COMMIT();

    int rA = warpM * 32 + (lane >> 2);
    int rB = warpN * 64 + (lane >> 2);
    int kq = lane & 3;

    for (int t = 0; t < T; t++) {
        int buf = t & 1;
        if (t + 1 < T) load_tile(t + 1, buf ^ 1);
        CP_COMMIT();
        CP_WAIT1();
        __syncthreads();

        const float* sA = smf + buf * STAGE_F;
        const float* sB = sA + TILE_F;

        #pragma unroll
        for (int kk = 0; kk < 4; kk++) {
            int c0 = kk * 8 + kq;
            uint32_t af[2][4];
            #pragma unroll
            for (int mt = 0; mt < 2; mt++) {
                int r = rA + mt * 16;
                af[mt][0] = f2tf(sA[r * LDP + c0]);
                af[mt][1] = f2tf(sA[(r + 8) * LDP + c0]);
                af[mt][2] = f2tf(sA[r * LDP + c0 + 4]);
                af[mt][3] = f2tf(sA[(r + 8) * LDP + c0 + 4]);
            }
            uint32_t bf[8][2];
            #pragma unroll
            for (int nt = 0; nt < 8; nt++) {
                int r = rB + nt * 8;
                bf[nt][0] = f2tf(sB[r * LDP + c0]);
                bf[nt][1] = f2tf(sB[r * LDP + c0 + 4]);
            }
            #pragma unroll
            for (int mt = 0; mt < 2; mt++)
                #pragma unroll
                for (int nt = 0; nt < 8; nt++)
                    mma8(acc[mt][nt], af[mt], bf[nt]);
        }
        __syncthreads();
    }

    // epilogue: thread owns rows (g, g+8) of each m16 tile, cols (lane%4)*2,+1
    #pragma unroll
    for (int mt = 0; mt < 2; mt++) {
        #pragma unroll
        for (int half = 0; half < 2; half++) {
            int row = m0 + warpM * 32 + mt * 16 + (lane >> 2) + half * 8;
            if (row >= Mrows) continue;
            int bI = (row >= Nn) ? 1 : 0;
            #pragma unroll
            for (int nt = 0; nt < 8; nt++) {
                int col = n0 + warpN * 64 + nt * 8 + (lane & 3) * 2;
                float v0 = acc[mt][nt][half * 2];
                float v1 = acc[mt][nt][half * 2 + 1];
                if (BIAS) { v0 += bias[col]; v1 += bias[col + 1]; }
                if (EPI == 1) {
                    v0 = v0 / (1.f + __expf(-v0));
                    v1 = v1 / (1.f + __expf(-v1));
                }
                if (EPI == 2) {
                    v0 += res[(size_t)row * Nout + col];
                    v1 += res[(size_t)row * Nout + col + 1];
                }
                if (EPI == 3) {
                    v0 = res[(size_t)row * Nout + col]     + gate[bI * gateStride + col]     * v0;
                    v1 = res[(size_t)row * Nout + col + 1] + gate[bI * gateStride + col + 1] * v1;
                }
                *(float2*)&O[(size_t)row * Nout + col] = make_float2(v0, v1);
            }
        }
    }
}

// ---------------------------------------------------------------------------
// m = sst + t
// ---------------------------------------------------------------------------
__global__ void mod_kernel(const float* __restrict__ t, const float* __restrict__ sst)
{
    int i = blockIdx.x * 256 + threadIdx.x;
    if (i < Bb * 6 * Cc) g_mb[i] = sst[i % (6 * Cc)] + t[i];
}

// ---------------------------------------------------------------------------
// LayerNorm + adaLN modulate
// ---------------------------------------------------------------------------
__global__ __launch_bounds__(256)
void ln_mod_kernel(const float* __restrict__ in, float* __restrict__ out,
                   int scRow, int shRow)
{
    int row = blockIdx.x;
    int b   = row / Nn;
    const float* xr = in + (size_t)row * Cc;

    float s = 0.f, s2 = 0.f;
    for (int c = threadIdx.x; c < Cc; c += blockDim.x) {
        float v = xr[c]; s += v; s2 += v * v;
    }
    __shared__ float sh1[8], sh2[8];
    int lane = threadIdx.x & 31, wid = threadIdx.x >> 5;
    #pragma unroll
    for (int o = 16; o > 0; o >>= 1) {
        s  += __shfl_down_sync(0xffffffffu, s,  o);
        s2 += __shfl_down_sync(0xffffffffu, s2, o);
    }
    if (lane == 0) { sh1[wid] = s; sh2[wid] = s2; }
    __syncthreads();
    if (wid == 0) {
        s  = (lane < 8) ? sh1[lane] : 0.f;
        s2 = (lane < 8) ? sh2[lane] : 0.f;
        #pragma unroll
        for (int o = 4; o > 0; o >>= 1) {
            s  += __shfl_down_sync(0xffffffffu, s,  o);
            s2 += __shfl_down_sync(0xffffffffu, s2, o);
        }
        if (lane == 0) { sh1[0] = s; sh2[0] = s2; }
    }
    __syncthreads();
    float mu   = sh1[0] * (1.f / Cc);
    float var  = sh2[0] * (1.f / Cc) - mu * mu;
    float rstd = rsqrtf(var + 1e-6f);
    const float* mbp = g_mb + (size_t)b * 6 * Cc;
    for (int c = threadIdx.x; c < Cc; c += blockDim.x) {
        float sc = mbp[scRow * Cc + c];
        float sv = mbp[shRow * Cc + c];
        out[(size_t)row * Cc + c] = (xr[c] - mu) * rstd * (1.f + sc) + sv;
    }
}

// ---------------------------------------------------------------------------
// SIMT GEMM (attention batched GEMMs)
// ---------------------------------------------------------------------------
template<bool TRANSB, bool BIAS, int EPI>
__global__ __launch_bounds__(256)
void gemm_k(const float* __restrict__ A, const float* __restrict__ Bm,
            const float* __restrict__ bias, const float* __restrict__ res,
            const float* __restrict__ gate, float* __restrict__ O,
            int Mrows, int Nout, int K, int lda, int ldb, int ldo,
            int HB, long aBs, long aHs, long bBs, long bHs, long oBs, long oHs,
            int gateStride)
{
    __shared__ float As[8][128];
    __shared__ float Bs[8][128];
    if (gridDim.z > 1) {
        int z = blockIdx.z;
        int bI = z / HB, hI = z % HB;
        A  += bI * aBs + hI * aHs;
        Bm += bI * bBs + hI * bHs;
        O  += bI * oBs + hI * oHs;
    }
    int m0  = blockIdx.y * 128;
    int n0  = blockIdx.x * 128;
    int tid = threadIdx.x;
    int tx  = tid & 15, ty = tid >> 4;
    int lr  = tid >> 1;
    int lk  = (tid & 1) * 4;
    int nk  = tid >> 5;
    int nj  = (tid & 31) * 4;

    float acc[8][8];
    #pragma unroll
    for (int i = 0; i < 8; i++)
        #pragma unroll
        for (int j = 0; j < 8; j++) acc[i][j] = 0.f;

    for (int k0 = 0; k0 < K; k0 += 8) {
        {
            int gr = m0 + lr;
            #pragma unroll
            for (int i = 0; i < 4; i++) {
                int gk = k0 + lk + i;
                As[lk + i][lr] = (gr < Mrows && gk < K) ? A[(long)gr * lda + gk] : 0.f;
            }
        }
        if (TRANSB) {
            int gj = n0 + lr;
            #pragma unroll
            for (int i = 0; i < 4; i++) {
                int gk = k0 + lk + i;
                Bs[lk + i][lr] = (gj < Nout && gk < K) ? Bm[(long)gj * ldb + gk] : 0.f;
            }
        } else {
            int gk = k0 + nk;
            #pragma unroll
            for (int i = 0; i < 4; i++) {
                int gj = n0 + nj + i;
                Bs[nk][nj + i] = (gk < K && gj < Nout) ? Bm[(long)gk * ldb + gj] : 0.f;
            }
        }
        __syncthreads();
        #pragma unroll
        for (int kk = 0; kk < 8; kk++) {
            float af[8], bf[8];
            *(float4*)&af[0] = *(const float4*)&As[kk][ty * 8];
            *(float4*)&af[4] = *(const float4*)&As[kk][ty * 8 + 4];
            *(float4*)&bf[0] = *(const float4*)&Bs[kk][tx * 8];
            *(float4*)&bf[4] = *(const float4*)&Bs[kk][tx * 8 + 4];
            #pragma unroll
            for (int i = 0; i < 8; i++)
                #pragma unroll
                for (int j = 0; j < 8; j++)
                    acc[i][j] = fmaf(af[i], bf[j], acc[i][j]);
        }
        __syncthreads();
    }

    #pragma unroll
    for (int i = 0; i < 8; i++) {
        int row = m0 + ty * 8 + i;
        if (row >= Mrows) continue;
        #pragma unroll
        for (int j = 0; j < 8; j++) {
            int col = n0 + tx * 8 + j;
            if (col >= Nout) continue;
            float v = acc[i][j];
            if (BIAS) v += bias[col];
            if (EPI == 1) v = v / (1.f + __expf(-v));
            if (EPI == 2) v = res[(long)row * ldo + col] + v;
            if (EPI == 3) {
                int bI = row / Nn;
                v = res[(long)row * ldo + col] + gate[bI * gateStride + col] * v;
            }
            O[(long)row * ldo + col] = v;
        }
    }
}

// ---------------------------------------------------------------------------
// LiteLA vk accumulation + epilogue
// ---------------------------------------------------------------------------
__global__ void zero_vk_kernel()
{
    int i = blockIdx.x * 256 + threadIdx.x;
    if (i < Bb * HLA * 33 * 32) g_vk[i] = 0.f;
}

__global__ __launch_bounds__(256)
void vk_kernel(const float* __restrict__ qkv, float* __restrict__ vkout)
{
    int bh = blockIdx.x;
    int b  = bh / HLA, h = bh % HLA;
    int split = blockIdx.y;
    __shared__ float ks[32][33];
    __shared__ float vs[32][33];
    float acc[5] = {0.f, 0.f, 0.f, 0.f, 0.f};
    int tid = threadIdx.x;
    const size_t base = (size_t)b * Nn * 3 * Cc;
    int nStart = split * (Nn / 16);
    for (int n0 = nStart; n0 < nStart + Nn / 16; n0 += 32) {
        for (int li = tid; li < 1024; li += 256) {
            int nn = li >> 5, dc = li & 31;
            size_t off = base + (size_t)(n0 + nn) * 3 * Cc + h * 32 + dc;
            ks[nn][dc] = fmaxf(qkv[off + Cc], 0.f);
            vs[nn][dc] = qkv[off + 2 * Cc];
        }
        __syncthreads();
        #pragma unroll
        for (int u = 0; u < 5; u++) {
            int idx = tid + 256 * u;
            if (idx < 1056) {
                int e = idx >> 5, dc = idx & 31;
                float a = acc[u];
                if (e == 32) {
                    #pragma unroll
                    for (int nn = 0; nn < 32; nn++) a += ks[nn][dc];
                } else {
                    #pragma unroll
                    for (int nn = 0; nn < 32; nn++) a += vs[nn][e] * ks[nn][dc];
                }
                acc[u] = a;
            }
        }
        __syncthreads();
    }
    #pragma unroll
    for (int u = 0; u < 5; u++) {
        int idx = tid + 256 * u;
        if (idx < 1056) {
            int e = idx >> 5, dc = idx & 31;
            atomicAdd(&vkout[((size_t)bh * 33 + e) * 32 + dc], acc[u]);
        }
    }
}

__global__ __launch_bounds__(256)
void la_out_kernel(const float* __restrict__ qkv, const float* __restrict__ vk,
                   float* __restrict__ out)
{
    int row = blockIdx.x;
    int b   = row / Nn;
    __shared__ float q[Cc];
    __shared__ float den[HLA];
    const float* qr = qkv + (size_t)row * 3 * Cc;
    for (int c = threadIdx.x; c < Cc; c += blockDim.x) q[c] = fmaxf(qr[c], 0.f);
    __syncthreads();
    if (threadIdx.x < HLA) {
        int h = threadIdx.x;
        const float* vkh = vk + ((size_t)(b * HLA + h) * 33 + 32) * 32;
        float s = 0.f;
        #pragma unroll
        for (int d = 0; d < 32; d++) s += vkh[d] * q[h * 32 + d];
        den[h] = s + 1e-8f;
    }
    __syncthreads();
    for (int c = threadIdx.x; c < Cc; c += blockDim.x) {
        int h = c >> 5, dd = c & 31;
        const float* vkr = vk + ((size_t)(b * HLA + h) * 33 + dd) * 32;
        const float* qh  = q + h * 32;
        float s = 0.f;
        #pragma unroll
        for (int d = 0; d < 32; d++) s += vkr[d] * qh[d];
        out[(size_t)row * Cc + c] = s / den[h];
    }
}

// ---------------------------------------------------------------------------
// Cross-attn softmax (one warp per row)
// ---------------------------------------------------------------------------
__global__ __launch_bounds__(256)
void softmax_kernel(float* __restrict__ s, long rows)
{
    long gw  = ((long)blockIdx.x * blockDim.x + threadIdx.x) >> 5;
    int lane = threadIdx.x & 31;
    if (gw >= rows) return;
    float* r = s + gw * Mkv;
    const float scale = 0.11785113019775793f;
    float v[10];
    float mx = -1e30f;
    #pragma unroll
    for (int i = 0; i < 10; i++) {
        int m = lane + 32 * i;
        v[i] = (m < Mkv) ? r[m] * scale : -1e30f;
        mx = fmaxf(mx, v[i]);
    }
    #pragma unroll
    for (int o = 16; o > 0; o >>= 1) mx = fmaxf(mx, __shfl_xor_sync(0xffffffffu, mx, o));
    float sum = 0.f;
    #pragma unroll
    for (int i = 0; i < 10; i++) { v[i] = __expf(v[i] - mx); sum += v[i]; }
    #pragma unroll
    for (int o = 16; o > 0; o >>= 1) sum += __shfl_xor_sync(0xffffffffu, sum, o);
    float inv = 1.f / sum;
    #pragma unroll
    for (int i = 0; i < 10; i++) {
        int m = lane + 32 * i;
        if (m < Mkv) r[m] = v[i] * inv;
    }
}

// ---------------------------------------------------------------------------
// depthwise 3x3 + bias + GLU
// ---------------------------------------------------------------------------
__global__ __launch_bounds__(256)
void dwglu_kernel(const float* __restrict__ h, const float* __restrict__ dww,
                  const float* __restrict__ dwb, float* __restrict__ out)
{
    long idx = (long)blockIdx.x * 256 + threadIdx.x;
    if (idx >= (long)Bb * Nn * HIDd) return;
    int  ch = (int)(idx % HIDd);
    long bn = idx / HIDd;
    int  n  = (int)(bn % Nn);
    int  b  = (int)(bn / Nn);
    int  y  = n >> 6, x = n & 63;
    float accA = dwb[ch];
    float accG = dwb[ch + HIDd];
    const float* wA = dww + (size_t)ch * 9;
    const float* wG = dww + (size_t)(ch + HIDd) * 9;
    #pragma unroll
    for (int dy = -1; dy <= 1; dy++) {
        int yy = y + dy;
        if (yy < 0 || yy > 63) continue;
        #pragma unroll
        for (int dx = -1; dx <= 1; dx++) {
            int xx = x + dx;
            if (xx < 0 || xx > 63) continue;
            size_t off = ((size_t)b * Nn + yy * 64 + xx) * (2 * HIDd);
            int w = (dy + 1) * 3 + (dx + 1);
            accA += h[off + ch]        * wA[w];
            accG += h[off + ch + HIDd] * wG[w];
        }
    }
    out[idx] = accA * (accG / (1.f + __expf(-accG)));
}

// ---------------------------------------------------------------------------
extern "C" void kernel_launch(void* const* d_in, const int* /*in_sizes*/, int /*n_in*/,
                              void* d_out, int /*out_size*/)
{
    const float* x       = (const float*)d_in[0];
    const float* y       = (const float*)d_in[1];
    const float* t       = (const float*)d_in[2];
    const float* sst     = (const float*)d_in[3];
    const float* qkv_w   = (const float*)d_in[4];
    const float* aproj_w = (const float*)d_in[5];
    const float* aproj_b = (const float*)d_in[6];
    const float* q_w     = (const float*)d_in[7];
    const float* q_b     = (const float*)d_in[8];
    const float* kv_w    = (const float*)d_in[9];
    const float* kv_b    = (const float*)d_in[10];
    const float* cproj_w = (const float*)d_in[11];
    const float* cproj_b = (const float*)d_in[12];
    const float* inv_w   = (const float*)d_in[13];
    const float* inv_b   = (const float*)d_in[14];
    const float* dw_w    = (const float*)d_in[15];
    const float* dw_b    = (const float*)d_in[16];
    const float* pw_w    = (const float*)d_in[17];
    float* out = (float*)d_out;

    float *p_big, *p_sh, *p_x1, *p_x2, *p_glu, *p_kv, *p_vk, *p_m;
    cudaGetSymbolAddress((void**)&p_big, g_big);
    cudaGetSymbolAddress((void**)&p_sh,  g_sh);
    cudaGetSymbolAddress((void**)&p_x1,  g_x1);
    cudaGetSymbolAddress((void**)&p_x2,  g_x2);
    cudaGetSymbolAddress((void**)&p_glu, g_glu);
    cudaGetSymbolAddress((void**)&p_kv,  g_kvb);
    cudaGetSymbolAddress((void**)&p_vk,  g_vk);
    cudaGetSymbolAddress((void**)&p_m,   g_mb);

    cudaFuncSetAttribute(mma_gemm<false,0>, cudaFuncAttributeMaxDynamicSharedMemorySize, MM_SMEM);
    cudaFuncSetAttribute(mma_gemm<true, 0>, cudaFuncAttributeMaxDynamicSharedMemorySize, MM_SMEM);
    cudaFuncSetAttribute(mma_gemm<true, 1>, cudaFuncAttributeMaxDynamicSharedMemorySize, MM_SMEM);
    cudaFuncSetAttribute(mma_gemm<true, 2>, cudaFuncAttributeMaxDynamicSharedMemorySize, MM_SMEM);
    cudaFuncSetAttribute(mma_gemm<true, 3>, cudaFuncAttributeMaxDynamicSharedMemorySize, MM_SMEM);
    cudaFuncSetAttribute(mma_gemm<false,3>, cudaFuncAttributeMaxDynamicSharedMemorySize, MM_SMEM);

    const int ROWS = Bb * Nn;  // 8192

    mod_kernel<<<(Bb * 6 * Cc + 255) / 256, 256>>>(t, sst);
    ln_mod_kernel<<<ROWS, 256>>>(x, p_sh, 1, 0);

    // qkv = xmod1 @ qkv_w.T
    mma_gemm<false,0><<<dim3(27, 64), 256, MM_SMEM>>>(
        p_sh, qkv_w, nullptr, nullptr, nullptr, p_big, ROWS, 3 * Cc, Cc, 0);

    zero_vk_kernel<<<(Bb * HLA * 33 * 32 + 255) / 256, 256>>>();
    vk_kernel<<<dim3(Bb * HLA, 16), 256>>>(p_big, p_vk);
    la_out_kernel<<<ROWS, 256>>>(p_big, p_vk, p_sh);

    // x1 = x + g_a * (la @ aproj_w.T + b)
    mma_gemm<true,3><<<dim3(9, 64), 256, MM_SMEM>>>(
        p_sh, aproj_w, aproj_b, x, p_m + 2 * Cc, p_x1, ROWS, Cc, Cc, 6 * Cc);

    // q = x1 @ q_w.T + q_b
    mma_gemm<true,0><<<dim3(9, 64), 256, MM_SMEM>>>(
        p_x1, q_w, q_b, nullptr, nullptr, p_sh, ROWS, Cc, Cc, 0);

    // kv = y @ kv_w.T + kv_b
    mma_gemm<true,0><<<dim3(18, 5), 256, MM_SMEM>>>(
        y, kv_w, kv_b, nullptr, nullptr, p_kv, Bb * Mkv, 2 * Cc, Cc, 0);

    // scores[b,h] = q @ k.T (batched, SIMT)
    gemm_k<true, false, 0><<<dim3(3, 32, Bb * HX), 256>>>(
        p_sh, p_kv, nullptr, nullptr, nullptr, p_big,
        Nn, Mkv, 72, Cc, 2 * Cc, Mkv,
        HX, (long)Nn * Cc, 72, (long)Mkv * 2 * Cc, 72,
        (long)HX * Nn * Mkv, (long)Nn * Mkv, 0);

    softmax_kernel<<<(Bb * HX * Nn) / 8, 256>>>(p_big, (long)Bb * HX * Nn);

    // o[b,h] = a @ v (batched NN, SIMT)
    gemm_k<false, false, 0><<<dim3(1, 32, Bb * HX), 256>>>(
        p_big, p_kv + Cc, nullptr, nullptr, nullptr, p_sh,
        Nn, 72, Mkv, Mkv, 2 * Cc, Cc,
        HX, (long)HX * Nn * Mkv, (long)Nn * Mkv, (long)Mkv * 2 * Cc, 72,
        (long)Nn * Cc, 72, 0);

    // x2 = x1 + o @ cproj_w.T + b
    mma_gemm<true,2><<<dim3(9, 64), 256, MM_SMEM>>>(
        p_sh, cproj_w, cproj_b, p_x1, nullptr, p_x2, ROWS, Cc, Cc, 0);

    ln_mod_kernel<<<ROWS, 256>>>(p_x2, p_sh, 4, 3);

    // h = silu(xmod2 @ inv_w.T + b)
    mma_gemm<true,1><<<dim3(45, 64), 256, MM_SMEM>>>(
        p_sh, inv_w, inv_b, nullptr, nullptr, p_big, ROWS, 2 * HIDd, Cc, 0);

    dwglu_kernel<<<(int)(((long)Bb * Nn * HIDd + 255) / 256), 256>>>(
        p_big, dw_w, dw_b, p_glu);

    // out = x2 + g_m * (glu @ pw_w.T)
    mma_gemm<false,3><<<dim3(9, 64), 256, MM_SMEM>>>(
        p_glu, pw_w, nullptr, p_x2, p_m + 5 * Cc, out, ROWS, Cc, HIDd, 6 * Cc);
}